// round 16
// baseline (speedup 1.0000x reference)
#include <cuda_runtime.h>
#include <math.h>

#define NSEG    2047
#define NPIX    16384
#define NTILE   256          // 16 x 16 tiles of 8x8 px
#define NCAP    640          // smem candidate capacity per transform
#define GAMMA4  800.0f       // gamma * 4 (raw-space d^2 = true d^2 / 4)
#define STEPR   (1.0f / 127.0f)            // raw-space grid step
// tile = 8x8 px, center (+3.5,+3.5): 2*half-diag = 7*sqrt(2) px (raw units)
#define THR_ADD (9.899495f * STEPR + 5e-4f)
#define FINF    __int_as_float(0x7F800000)

__device__ __forceinline__ float satmul(float a, float b) {
    float r; asm("mul.rn.sat.f32 %0,%1,%2;" : "=f"(r) : "f"(a), "f"(b)); return r;
}
// half-private barrier: 256 threads of one w-half (ids 1 and 2)
__device__ __forceinline__ void half_bar(int w) {
    asm volatile("bar.sync %0, 256;" :: "r"(w + 1) : "memory");
}

// Cross-CTA state (graph-replay safe: reset by last CTA each run).
__device__ float    g_loss = 0.0f;
__device__ unsigned g_done = 0;

// ---------------------------------------------------------------------------
// grid 256 x 512: CTA = one 8x8-px tile, BOTH transforms.
// Threads 0-255 (warps 0-7) handle w=0; 256-511 (warps 8-15) handle w=1.
// Phases 1-2 half-private (named barriers). Phase 2 is unrolled x2 over the
// candidate list (padded to a multiple of 64): two independent LDS pairs in
// flight per iteration to cover shared-memory latency.
// Loss computed by warp 0 (2 px/lane), one atomicAdd per CTA; 256th CTA
// writes out[0] and resets. All math in RAW [0,1] space (gamma*4).
// ---------------------------------------------------------------------------
__global__ void __launch_bounds__(512, 2) fused_kernel(const float* __restrict__ pred,
                                                       const float* __restrict__ gt,
                                                       float* __restrict__ out) {
    const int tid  = threadIdx.x;
    const int tile = blockIdx.x;
    const int tx = tile & 15, ty = tile >> 4;

    const int w    = tid >> 8;          // 0: pred, 1: gt
    const int t256 = tid & 255;
    const float* __restrict__ c = w ? gt : pred;

    const float cxr = ((float)(tx * 8) + 3.5f) * STEPR;
    const float cyr = ((float)(ty * 8) + 3.5f) * STEPR;

    const int rowi = (tid >> 5) & 7;    // warp-within-half = pixel row
    const int h    = tid & 31;          // lane = candidate slice
    const float gyr = (float)(ty * 8 + rowi) * STEPR;

    __shared__ float4 s_seg[2][NCAP];                     // 20 KB
    __shared__ float  s_inv[2][NCAP];                     //  5 KB
    __shared__ unsigned short s_ovf[2][NSEG - NCAP + 1];  // ~5.5 KB cold
    __shared__ float  s_q[2][64];
    __shared__ float  s_red[16];
    __shared__ int    s_cnt[2];

    if (t256 == 0) s_cnt[w] = 0;        // each half resets its own counter

    // ---- Phase 1a: stage 28 floats (points 8t..8t+9) via 7 LDG.128 ----
    const float4* __restrict__ c4 = (const float4*)c;
    float f[28];
#pragma unroll
    for (int q = 0; q < 7; ++q) {
        int idx = 6 * t256 + q;
        if (idx > 1535) idx = 1535;     // tail clamp; only affects guarded seg 2047
        const float4 v4 = __ldg(&c4[idx]);
        f[q * 4 + 0] = v4.x; f[q * 4 + 1] = v4.y;
        f[q * 4 + 2] = v4.z; f[q * 4 + 3] = v4.w;
    }

    // ---- Phase 1b: center eval in raw space ----
    float d2c[8];
    float lmin = FINF;
#pragma unroll
    for (int k = 0; k < 8; ++k) {
        const int s = 8 * t256 + k;
        float d2 = FINF;
        const float pen = f[k * 3 + 2];
        const bool masked = w ? (pen != 0.0f) : (pen > 0.5f);
        if (s < NSEG && !masked) {
            const float pjx = f[k * 3 + 3];
            const float pjy = f[k * 3 + 4];
            const float vx  = f[k * 3 + 0] - pjx;
            const float vy  = f[k * 3 + 1] - pjy;
            const float vn  = vx * vx + vy * vy;
            const float inv = __fdividef(1.0f, vn);  // vn=0 -> inf; sat(NaN)=0 -> t=0 exact
            const float ux = cxr - pjx, uy = cyr - pjy;
            const float uv = fmaf(ux, vx, uy * vy);
            const float t  = satmul(uv, inv);
            const float dx = fmaf(-t, vx, ux);
            const float dy = fmaf(-t, vy, uy);
            d2 = fmaf(dy, dy, dx * dx);
        }
        d2c[k] = d2;
        lmin = fminf(lmin, d2);
    }
#pragma unroll
    for (int o = 16; o > 0; o >>= 1)
        lmin = fminf(lmin, __shfl_xor_sync(0xFFFFFFFFu, lmin, o));
    if (h == 0) s_red[tid >> 5] = lmin;
    half_bar(w);                                        // #1 (half-private)
    const int ubase = w * 8;
    float U = s_red[ubase];
#pragma unroll
    for (int q = 1; q < 8; ++q) U = fminf(U, s_red[ubase + q]);
    const float thd = sqrtf(U) + THR_ADD;
    const float thr = thd * thd;

    // ---- Phase 1c: survivors -> smem straight from registers ----
#pragma unroll
    for (int k = 0; k < 8; ++k) {
        if (d2c[k] < thr) {
            const int pos = atomicAdd(&s_cnt[w], 1);
            if (pos < NCAP) {
                const float pjx = f[k * 3 + 3];
                const float pjy = f[k * 3 + 4];
                const float vx  = f[k * 3 + 0] - pjx;
                const float vy  = f[k * 3 + 1] - pjy;
                const float vn  = vx * vx + vy * vy;
                s_seg[w][pos] = make_float4(pjx, pjy, vx, vy);
                s_inv[w][pos] = __fdividef(1.0f, vn);
            } else {
                s_ovf[w][pos - NCAP] = (unsigned short)(8 * t256 + k);
            }
        }
    }
    half_bar(w);                                        // #2 (half-private)

    // pad this w's candidate list to a multiple of 64 with far dummies
    const int len  = s_cnt[w];
    const int n1   = (len < NCAP) ? len : NCAP;
    const int npad = (n1 + 63) & ~63;                   // NCAP%64==0 -> npad<=NCAP
    if (t256 < npad - n1) {
        s_seg[w][n1 + t256] = make_float4(1e9f, 1e9f, 0.0f, 0.0f);
        s_inv[w][n1 + t256] = 0.0f;
    }
    half_bar(w);                                        // #3 (half-private)

    // ---- Phase 2: warp=row, lane=slice; unroll x2, paired LDS in flight ----
    float gxr[8], m[8];
#pragma unroll
    for (int k = 0; k < 8; ++k) {
        gxr[k] = (float)(tx * 8 + k) * STEPR;
        m[k]   = FINF;
    }

    for (int j = h; j < npad; j += 64) {
        const float4 qa  = s_seg[w][j];
        const float  ia  = s_inv[w][j];
        const float4 qb  = s_seg[w][j + 32];
        const float  ib  = s_inv[w][j + 32];

        const float uya  = gyr - qa.y;
        const float cyva = uya * qa.w;
#pragma unroll
        for (int k = 0; k < 8; ++k) {
            const float ux = gxr[k] - qa.x;
            const float uv = fmaf(ux, qa.z, cyva);
            const float t  = satmul(uv, ia);
            const float dx = fmaf(-t, qa.z, ux);
            const float dy = fmaf(-t, qa.w, uya);
            m[k] = fminf(m[k], fmaf(dy, dy, dx * dx));
        }
        const float uyb  = gyr - qb.y;
        const float cyvb = uyb * qb.w;
#pragma unroll
        for (int k = 0; k < 8; ++k) {
            const float ux = gxr[k] - qb.x;
            const float uv = fmaf(ux, qb.z, cyvb);
            const float t  = satmul(uv, ib);
            const float dx = fmaf(-t, qb.z, ux);
            const float dy = fmaf(-t, qb.w, uyb);
            m[k] = fminf(m[k], fmaf(dy, dy, dx * dx));
        }
    }

    // cold overflow path (len > NCAP; not hit on this data, exact if hit)
    if (len > NCAP) {
        const int novf = len - NCAP;
        for (int o2 = 0; o2 < novf; ++o2) {
            const int s = s_ovf[w][o2];
            const float pjx = __ldg(&c[s * 3 + 3]);
            const float pjy = __ldg(&c[s * 3 + 4]);
            const float vx  = __ldg(&c[s * 3 + 0]) - pjx;
            const float vy  = __ldg(&c[s * 3 + 1]) - pjy;
            const float vn  = vx * vx + vy * vy;
            const float inv = __fdividef(1.0f, vn);
            const float uy  = gyr - pjy;
            const float cyv = uy * vy;
#pragma unroll
            for (int k = 0; k < 8; ++k) {
                const float ux = gxr[k] - pjx;
                const float uv = fmaf(ux, vx, cyv);
                const float t  = satmul(uv, inv);
                const float dx = fmaf(-t, vx, ux);
                const float dy = fmaf(-t, vy, uy);
                m[k] = fminf(m[k], fmaf(dy, dy, dx * dx));
            }
        }
    }

    // ---- warp shuffle-min across 32 slices ----
#pragma unroll
    for (int o = 16; o > 0; o >>= 1) {
#pragma unroll
        for (int k = 0; k < 8; ++k)
            m[k] = fminf(m[k], __shfl_xor_sync(0xFFFFFFFFu, m[k], o));
    }
    if (h < 8)
        s_q[w][rowi * 8 + h] = m[h];    // pixel (rowi, h) of transform w
    __syncthreads();                    // full-block: loss reads both halves

    // ---- loss over 64 pixels, warp 0 only (2 px/lane), one atomicAdd ----
    if (tid < 32) {
        const float b0a = __expf(-GAMMA4 * s_q[0][tid]);
        const float b1a = __expf(-GAMMA4 * s_q[1][tid]);
        const float b0b = __expf(-GAMMA4 * s_q[0][tid + 32]);
        const float b1b = __expf(-GAMMA4 * s_q[1][tid + 32]);
        const float da = b0a - b1a;
        const float db = b0b - b1b;
        float v = fmaf(da, da, db * db);
#pragma unroll
        for (int o = 16; o > 0; o >>= 1)
            v += __shfl_xor_sync(0xFFFFFFFFu, v, o);
        if (tid == 0) {
            atomicAdd(&g_loss, v);
            __threadfence();
            const unsigned old = atomicAdd(&g_done, 1u);
            if (old == NTILE - 1) {
                const float total = *((volatile float*)&g_loss);
                out[0] = total * (1.0f / (float)NPIX);
                g_loss = 0.0f;
                g_done = 0u;
            }
        }
    }
}

// ---------------------------------------------------------------------------
extern "C" void kernel_launch(void* const* d_in, const int* in_sizes, int n_in,
                              void* d_out, int out_size) {
    const float* pred = (const float*)d_in[0];
    const float* gt   = (const float*)d_in[1];
    float* out = (float*)d_out;

    fused_kernel<<<NTILE, 512>>>(pred, gt, out);
}